// round 1
// baseline (speedup 1.0000x reference)
#include <cuda_runtime.h>
#include <cuda_bf16.h>

#define Nn 20000
#define Ee 640000
#define Hh 128
#define Gg 128
#define Cc 2
#define Ll 3
#define BN_EPS 1e-5f

// ---------------- scratch (static device globals; no runtime alloc) --------
__device__ float g_h[Nn * Hh];      // layer input h
__device__ float g_A[Nn * Hh];      // aggregation target / gemm2 out
__device__ float g_B[Nn * Hh];      // gemm1 out
__device__ float g_colS[Hh];        // BN column sums
__device__ float g_colQ[Hh];        // BN column sumsq
__device__ float g_s[Hh];           // BN scale
__device__ float g_t[Hh];           // BN shift
__device__ float g_pool[Gg * Hh];   // pooled sums
__device__ float g_cnt[Gg];         // per-graph counts

// ---------------- setup: zero accumulators --------------------------------
__global__ void k_setup() {
    int t = threadIdx.x;
    if (t < Hh) { g_colS[t] = 0.f; g_colQ[t] = 0.f; }
    if (t < Gg) g_cnt[t] = 0.f;
    for (int i = t; i < Gg * Hh; i += blockDim.x) g_pool[i] = 0.f;
}

// ---------------- encoder: h = x*encW + encb ; A = (1+eps0)*h --------------
__global__ void k_enc(const float* __restrict__ x,
                      const float* __restrict__ W,
                      const float* __restrict__ b,
                      const float* __restrict__ eps) {
    int idx = blockIdx.x * blockDim.x + threadIdx.x;   // float4 id
    if (idx >= Nn * Hh / 4) return;
    int i = idx >> 5;       // node
    int c = idx & 31;       // column chunk (4 floats)
    float xv = x[i];
    float4 w4 = ((const float4*)W)[c];
    float4 b4 = ((const float4*)b)[c];
    float e0 = 1.0f + eps[0];
    float4 h4;
    h4.x = fmaf(xv, w4.x, b4.x);
    h4.y = fmaf(xv, w4.y, b4.y);
    h4.z = fmaf(xv, w4.z, b4.z);
    h4.w = fmaf(xv, w4.w, b4.w);
    ((float4*)g_h)[idx] = h4;
    float4 a4 = make_float4(e0 * h4.x, e0 * h4.y, e0 * h4.z, e0 * h4.w);
    ((float4*)g_A)[idx] = a4;
}

// ---------------- edge scatter: A[dst] += h[src]  (vector RED) -------------
__global__ void k_scatter(const int* __restrict__ ei) {
    int tid = blockIdx.x * blockDim.x + threadIdx.x;
    if (tid >= Ee * 32) return;
    int e = tid >> 5;          // edge id (32 threads per edge)
    int c = tid & 31;          // 4-float chunk
    int src = ei[e];
    int dst = ei[Ee + e];
    float4 v = *(const float4*)(g_h + (long)src * Hh + c * 4);
    float* p = g_A + (long)dst * Hh + c * 4;
    asm volatile("red.global.add.v4.f32 [%0], {%1,%2,%3,%4};"
                 :: "l"(p), "f"(v.x), "f"(v.y), "f"(v.z), "f"(v.w)
                 : "memory");
}

// ---------------- GEMM: Out = preop(A) @ W + bias; accumulate BN sums ------
// preop (usePre): v -> relu(g_s[k]*v + g_t[k]) applied to A elements (col k)
#define BM 64
#define BK 32
__global__ void k_gemm(const float* __restrict__ A,
                       const float* __restrict__ W,
                       const float* __restrict__ bias,
                       int usePre,
                       float* __restrict__ Out) {
    __shared__ float As[BK][BM];       // transposed A tile
    __shared__ float Bs[BK][Hh];
    __shared__ float shS[Hh];
    __shared__ float shQ[Hh];

    int tid = threadIdx.x;             // 256 threads
    int ty = tid >> 4;                 // 0..15 (row group)
    int tx = tid & 15;                 // 0..15 (col group)
    int row0 = blockIdx.x * BM;

    if (tid < Hh) { shS[tid] = 0.f; shQ[tid] = 0.f; }

    float acc[4][8];
#pragma unroll
    for (int m = 0; m < 4; m++)
#pragma unroll
        for (int n = 0; n < 8; n++) acc[m][n] = 0.f;

    for (int kk = 0; kk < Hh; kk += BK) {
        // load A tile (64 rows x 32 cols) transposed into As[k][r]
#pragma unroll
        for (int q = 0; q < 2; q++) {
            int flat = tid * 2 + q;            // 0..511 float4 ids
            int r = flat >> 3;                 // 0..63
            int k4 = flat & 7;                 // 0..7
            int gr = row0 + r;
            float4 v = make_float4(0.f, 0.f, 0.f, 0.f);
            if (gr < Nn) {
                v = *(const float4*)(A + (long)gr * Hh + kk + k4 * 4);
                if (usePre) {
                    float4 s4 = *(const float4*)(g_s + kk + k4 * 4);
                    float4 t4 = *(const float4*)(g_t + kk + k4 * 4);
                    v.x = fmaxf(fmaf(s4.x, v.x, t4.x), 0.f);
                    v.y = fmaxf(fmaf(s4.y, v.y, t4.y), 0.f);
                    v.z = fmaxf(fmaf(s4.z, v.z, t4.z), 0.f);
                    v.w = fmaxf(fmaf(s4.w, v.w, t4.w), 0.f);
                }
            }
            As[k4 * 4 + 0][r] = v.x;
            As[k4 * 4 + 1][r] = v.y;
            As[k4 * 4 + 2][r] = v.z;
            As[k4 * 4 + 3][r] = v.w;
        }
        // load B tile (32 rows x 128 cols)
#pragma unroll
        for (int q = 0; q < 4; q++) {
            int flat = q * 256 + tid;          // 0..1023 float4 ids
            int kr = flat >> 5;                // 0..31
            int c4 = flat & 31;                // 0..31
            *(float4*)&Bs[kr][c4 * 4] = *(const float4*)(W + (long)(kk + kr) * Hh + c4 * 4);
        }
        __syncthreads();

#pragma unroll
        for (int k = 0; k < BK; k++) {
            float4 a4 = *(const float4*)&As[k][ty * 4];
            float4 b0 = *(const float4*)&Bs[k][tx * 8];
            float4 b1 = *(const float4*)&Bs[k][tx * 8 + 4];
            float a[4] = {a4.x, a4.y, a4.z, a4.w};
            float bb[8] = {b0.x, b0.y, b0.z, b0.w, b1.x, b1.y, b1.z, b1.w};
#pragma unroll
            for (int m = 0; m < 4; m++)
#pragma unroll
                for (int n = 0; n < 8; n++)
                    acc[m][n] = fmaf(a[m], bb[n], acc[m][n]);
        }
        __syncthreads();
    }

    // epilogue: add bias, store, accumulate per-column sum/sumsq
    int col0 = tx * 8;
    float4 bi0 = ((const float4*)bias)[tx * 2];
    float4 bi1 = ((const float4*)bias)[tx * 2 + 1];
    float bb[8] = {bi0.x, bi0.y, bi0.z, bi0.w, bi1.x, bi1.y, bi1.z, bi1.w};
    float ps[8], pq[8];
#pragma unroll
    for (int n = 0; n < 8; n++) { ps[n] = 0.f; pq[n] = 0.f; }

#pragma unroll
    for (int m = 0; m < 4; m++) {
        int gr = row0 + ty * 4 + m;
        if (gr < Nn) {
            float v[8];
#pragma unroll
            for (int n = 0; n < 8; n++) {
                v[n] = acc[m][n] + bb[n];
                ps[n] += v[n];
                pq[n] += v[n] * v[n];
            }
            float4 o0 = make_float4(v[0], v[1], v[2], v[3]);
            float4 o1 = make_float4(v[4], v[5], v[6], v[7]);
            *(float4*)(Out + (long)gr * Hh + col0) = o0;
            *(float4*)(Out + (long)gr * Hh + col0 + 4) = o1;
        }
    }
#pragma unroll
    for (int n = 0; n < 8; n++) {
        atomicAdd(&shS[col0 + n], ps[n]);
        atomicAdd(&shQ[col0 + n], pq[n]);
    }
    __syncthreads();
    if (tid < Hh) {
        atomicAdd(&g_colS[tid], shS[tid]);
        atomicAdd(&g_colQ[tid], shQ[tid]);
    }
}

// ---------------- BN finalize: compute scale/shift, zero sums --------------
__global__ void k_bnfin(const float* __restrict__ gamma,
                        const float* __restrict__ beta) {
    int j = threadIdx.x;
    if (j >= Hh) return;
    float inv = 1.0f / (float)Nn;
    float mu = g_colS[j] * inv;
    float var = g_colQ[j] * inv - mu * mu;
    float sc = gamma[j] * rsqrtf(var + BN_EPS);
    g_s[j] = sc;
    g_t[j] = beta[j] - sc * mu;
    g_colS[j] = 0.f;
    g_colQ[j] = 0.f;
}

// ---------------- post: h = relu(bn2(A)); A = (1+eps_next)*h  OR  pool -----
__global__ void k_post(const float* __restrict__ eps, int next_l, int last,
                       const int* __restrict__ batch) {
    int idx = blockIdx.x * blockDim.x + threadIdx.x;   // float4 id
    if (idx >= Nn * Hh / 4) return;
    int i = idx >> 5;
    int c = idx & 31;
    float4 z = ((const float4*)g_A)[idx];
    float4 s4 = ((const float4*)g_s)[c];
    float4 t4 = ((const float4*)g_t)[c];
    float4 v;
    v.x = fmaxf(fmaf(s4.x, z.x, t4.x), 0.f);
    v.y = fmaxf(fmaf(s4.y, z.y, t4.y), 0.f);
    v.z = fmaxf(fmaf(s4.z, z.z, t4.z), 0.f);
    v.w = fmaxf(fmaf(s4.w, z.w, t4.w), 0.f);
    if (!last) {
        ((float4*)g_h)[idx] = v;
        float en = 1.0f + eps[next_l];
        float4 a4 = make_float4(en * v.x, en * v.y, en * v.z, en * v.w);
        ((float4*)g_A)[idx] = a4;
    } else {
        int g = batch[i];
        float* p = g_pool + (long)g * Hh + c * 4;
        asm volatile("red.global.add.v4.f32 [%0], {%1,%2,%3,%4};"
                     :: "l"(p), "f"(v.x), "f"(v.y), "f"(v.z), "f"(v.w)
                     : "memory");
        if (c == 0) atomicAdd(&g_cnt[g], 1.0f);
    }
}

// ---------------- classifier ----------------------------------------------
__global__ void k_cls(const float* __restrict__ W,
                      const float* __restrict__ b,
                      float* __restrict__ out) {
    int tid = threadIdx.x;      // 256 = G*C
    if (tid >= Gg * Cc) return;
    int g = tid >> 1;
    int cc = tid & 1;
    float inv = 1.0f / fmaxf(g_cnt[g], 1.0f);
    float acc = b[cc];
#pragma unroll 8
    for (int j = 0; j < Hh; j++)
        acc += g_pool[g * Hh + j] * inv * W[j * Cc + cc];
    out[g * Cc + cc] = acc;
}

// ---------------- launch ---------------------------------------------------
extern "C" void kernel_launch(void* const* d_in, const int* in_sizes, int n_in,
                              void* d_out, int out_size) {
    const float* x    = (const float*)d_in[0];
    const int*   ei   = (const int*)d_in[1];
    const int*   batch= (const int*)d_in[2];
    const float* encW = (const float*)d_in[3];
    const float* encb = (const float*)d_in[4];
    const float* W1   = (const float*)d_in[5];
    const float* b1   = (const float*)d_in[6];
    const float* g1   = (const float*)d_in[7];
    const float* be1  = (const float*)d_in[8];
    const float* W2   = (const float*)d_in[9];
    const float* b2   = (const float*)d_in[10];
    const float* eps  = (const float*)d_in[11];
    const float* bng  = (const float*)d_in[12];
    const float* bnb  = (const float*)d_in[13];
    const float* clsW = (const float*)d_in[14];
    const float* clsb = (const float*)d_in[15];
    float* out = (float*)d_out;

    float *pA = nullptr, *pB = nullptr;
    cudaGetSymbolAddress((void**)&pA, g_A);
    cudaGetSymbolAddress((void**)&pB, g_B);

    const int elemBlocks = (Nn * Hh / 4) / 256;          // 2500
    const int scatBlocks = (Ee * 32 + 255) / 256;        // 80000
    const int gemmBlocks = (Nn + BM - 1) / BM;           // 313

    k_setup<<<1, 256>>>();
    k_enc<<<elemBlocks, 256>>>(x, encW, encb, eps);
    for (int l = 0; l < Ll; l++) {
        k_scatter<<<scatBlocks, 256>>>(ei);
        k_gemm<<<gemmBlocks, 256>>>(pA, W1 + (long)l * Hh * Hh, b1 + l * Hh, 0, pB);
        k_bnfin<<<1, 128>>>(g1 + l * Hh, be1 + l * Hh);
        k_gemm<<<gemmBlocks, 256>>>(pB, W2 + (long)l * Hh * Hh, b2 + l * Hh, 1, pA);
        k_bnfin<<<1, 128>>>(bng + l * Hh, bnb + l * Hh);
        k_post<<<elemBlocks, 256>>>(eps, l + 1, (l == Ll - 1) ? 1 : 0, batch);
    }
    k_cls<<<1, 256>>>(clsW, clsb, out);
}

// round 2
// speedup vs baseline: 1.3929x; 1.3929x over previous
#include <cuda_runtime.h>
#include <cuda_bf16.h>

#define Nn 20000
#define Ee 640000
#define Hh 128
#define Gg 128
#define Cc 2
#define Ll 3
#define BN_EPS 1e-5f

// ---------------- scratch ---------------------------------------------------
__device__ float g_h[Nn * Hh];
__device__ float g_A[Nn * Hh];
__device__ float g_B[Nn * Hh];
__device__ float g_colS[Hh];
__device__ float g_colQ[Hh];
__device__ float g_s[Hh];
__device__ float g_t[Hh];
__device__ float g_pool[Gg * Hh];
__device__ float g_cnt[Gg];
__device__ int   g_deg[Nn];
__device__ float g_sx[Nn];
__device__ int   g_rowptr[Nn + 1];
__device__ int   g_cursor[Nn];
__device__ int   g_csrc[Ee];
__device__ float g_u[Hh];
__device__ float g_v[Hh];

// ---------------- setup -----------------------------------------------------
__global__ void k_setup() {
    int idx = blockIdx.x * blockDim.x + threadIdx.x;
    for (int i = idx; i < Nn; i += gridDim.x * blockDim.x) {
        g_deg[i] = 0; g_sx[i] = 0.f;
    }
    for (int i = idx; i < Gg * Hh; i += gridDim.x * blockDim.x) g_pool[i] = 0.f;
    if (idx < Hh) { g_colS[idx] = 0.f; g_colQ[idx] = 0.f; }
    if (idx < Gg) g_cnt[idx] = 0.f;
}

// ---------------- histogram: deg[dst]++, sx[dst]+=x[src] --------------------
__global__ void k_hist(const int* __restrict__ ei, const float* __restrict__ x) {
    int e = blockIdx.x * blockDim.x + threadIdx.x;
    if (e >= Ee) return;
    int src = ei[e];
    int dst = ei[Ee + e];
    atomicAdd(&g_deg[dst], 1);
    atomicAdd(&g_sx[dst], x[src]);
}

// ---------------- exclusive scan over deg -> rowptr, cursor -----------------
#define SCAN_CH 20
__global__ void k_scan() {
    __shared__ int sh[1024];
    int t = threadIdx.x;
    int base = t * SCAN_CH;
    int loc[SCAN_CH];
    int s = 0;
#pragma unroll
    for (int i = 0; i < SCAN_CH; i++) {
        int n = base + i;
        int d = (n < Nn) ? g_deg[n] : 0;
        loc[i] = s;
        s += d;
    }
    sh[t] = s;
    __syncthreads();
    for (int off = 1; off < 1024; off <<= 1) {
        int v = (t >= off) ? sh[t - off] : 0;
        __syncthreads();
        sh[t] += v;
        __syncthreads();
    }
    int excl = sh[t] - s;
#pragma unroll
    for (int i = 0; i < SCAN_CH; i++) {
        int n = base + i;
        if (n < Nn) {
            int r = excl + loc[i];
            g_rowptr[n] = r;
            g_cursor[n] = r;
        }
    }
    if (t == 1023) g_rowptr[Nn] = sh[1023];
}

// ---------------- fill CSR --------------------------------------------------
__global__ void k_fill(const int* __restrict__ ei) {
    int e = blockIdx.x * blockDim.x + threadIdx.x;
    if (e >= Ee) return;
    int dst = ei[Ee + e];
    int p = atomicAdd(&g_cursor[dst], 1);
    g_csrc[p] = ei[e];
}

// ---------------- prep: u = encW @ W1[0], v = encb @ W1[0] ------------------
__global__ void k_prep(const float* __restrict__ encW,
                       const float* __restrict__ encb,
                       const float* __restrict__ W1) {
    int j = threadIdx.x;
    float u = 0.f, v = 0.f;
#pragma unroll 8
    for (int k = 0; k < Hh; k++) {
        float w = W1[k * Hh + j];
        u = fmaf(encW[k], w, u);
        v = fmaf(encb[k], w, v);
    }
    g_u[j] = u;
    g_v[j] = v;
}

// ---------------- layer-1 collapsed linear + BN stats -----------------------
// z1[i][j] = a_i*u[j] + c_i*v[j] + b1[j],  a=(1+e0)x+sx, c=(1+e0)+deg
__global__ void k_l1(const float* __restrict__ x,
                     const float* __restrict__ b1,
                     const float* __restrict__ eps) {
    int j = threadIdx.x;                  // 0..127 (column)
    int i0 = blockIdx.x * 128;
    float u = g_u[j], v = g_v[j], bb = b1[j];
    float e0 = 1.0f + eps[0];
    float ps = 0.f, pq = 0.f;
#pragma unroll 4
    for (int r = 0; r < 128; r++) {
        int i = i0 + r;
        if (i >= Nn) break;
        float a = fmaf(e0, __ldg(&x[i]), g_sx[i]);
        float c = e0 + (float)g_deg[i];
        float z = fmaf(a, u, fmaf(c, v, bb));
        g_B[(long)i * Hh + j] = z;
        ps += z;
        pq += z * z;
    }
    atomicAdd(&g_colS[j], ps);
    atomicAdd(&g_colQ[j], pq);
}

// ---------------- gather: A = (1+eps_l)*h + sum_{src in N(i)} h[src] --------
__global__ void k_gather(const float* __restrict__ eps, int l) {
    __shared__ int sidx[128];
    int i = blockIdx.x;
    int j = threadIdx.x;
    int start = g_rowptr[i];
    int end = g_rowptr[i + 1];
    float acc = 0.f;
    for (int n0 = start; n0 < end; n0 += 128) {
        int count = min(128, end - n0);
        if (j < count) sidx[j] = g_csrc[n0 + j];
        __syncthreads();
        int t = 0;
        for (; t + 4 <= count; t += 4) {
            int s0 = sidx[t], s1 = sidx[t + 1], s2 = sidx[t + 2], s3 = sidx[t + 3];
            float v0 = g_h[(long)s0 * Hh + j];
            float v1 = g_h[(long)s1 * Hh + j];
            float v2 = g_h[(long)s2 * Hh + j];
            float v3 = g_h[(long)s3 * Hh + j];
            acc += (v0 + v1) + (v2 + v3);
        }
        for (; t < count; t++) acc += g_h[(long)sidx[t] * Hh + j];
        __syncthreads();
    }
    float el = 1.0f + eps[l];
    g_A[(long)i * Hh + j] = fmaf(el, g_h[(long)i * Hh + j], acc);
}

// ---------------- GEMM: Out = preop(A) @ W + bias; BN col sums --------------
#define BM 128
#define BK 16
__global__ __launch_bounds__(256) void k_gemm(const float* __restrict__ A,
                                              const float* __restrict__ W,
                                              const float* __restrict__ bias,
                                              int usePre,
                                              float* __restrict__ Out) {
    __shared__ float As[BK][132];      // padded, transposed (k-major)
    __shared__ float Bs[BK][Hh];
    __shared__ float shS[Hh];
    __shared__ float shQ[Hh];

    int tid = threadIdx.x;             // 256
    int tx = tid & 15;                 // col group
    int ty = tid >> 4;                 // row group
    int row0 = blockIdx.x * BM;

    if (tid < Hh) { shS[tid] = 0.f; shQ[tid] = 0.f; }

    float acc[8][8];
#pragma unroll
    for (int m = 0; m < 8; m++)
#pragma unroll
        for (int n = 0; n < 8; n++) acc[m][n] = 0.f;

    for (int kk = 0; kk < Hh; kk += BK) {
        // A tile: 128 rows x 16 k, transposed into As
#pragma unroll
        for (int q = 0; q < 2; q++) {
            int flat = tid * 2 + q;        // 0..511
            int r = flat >> 2;             // 0..127
            int k4 = flat & 3;             // 0..3
            int gr = row0 + r;
            float4 v = make_float4(0.f, 0.f, 0.f, 0.f);
            if (gr < Nn) {
                v = *(const float4*)(A + (long)gr * Hh + kk + k4 * 4);
                if (usePre) {
                    float4 s4 = *(const float4*)(g_s + kk + k4 * 4);
                    float4 t4 = *(const float4*)(g_t + kk + k4 * 4);
                    v.x = fmaxf(fmaf(s4.x, v.x, t4.x), 0.f);
                    v.y = fmaxf(fmaf(s4.y, v.y, t4.y), 0.f);
                    v.z = fmaxf(fmaf(s4.z, v.z, t4.z), 0.f);
                    v.w = fmaxf(fmaf(s4.w, v.w, t4.w), 0.f);
                }
            }
            As[k4 * 4 + 0][r] = v.x;
            As[k4 * 4 + 1][r] = v.y;
            As[k4 * 4 + 2][r] = v.z;
            As[k4 * 4 + 3][r] = v.w;
        }
        // B tile: 16 k x 128 cols
#pragma unroll
        for (int q = 0; q < 2; q++) {
            int flat = tid * 2 + q;        // 0..511
            int kr = flat >> 5;            // 0..15
            int c4 = flat & 31;            // 0..31
            *(float4*)&Bs[kr][c4 * 4] = *(const float4*)(W + (long)(kk + kr) * Hh + c4 * 4);
        }
        __syncthreads();

#pragma unroll
        for (int k = 0; k < BK; k++) {
            float4 a0 = *(const float4*)&As[k][ty * 8];
            float4 a1 = *(const float4*)&As[k][ty * 8 + 4];
            float4 b0 = *(const float4*)&Bs[k][tx * 8];
            float4 b1 = *(const float4*)&Bs[k][tx * 8 + 4];
            float a[8] = {a0.x, a0.y, a0.z, a0.w, a1.x, a1.y, a1.z, a1.w};
            float b[8] = {b0.x, b0.y, b0.z, b0.w, b1.x, b1.y, b1.z, b1.w};
#pragma unroll
            for (int m = 0; m < 8; m++)
#pragma unroll
                for (int n = 0; n < 8; n++)
                    acc[m][n] = fmaf(a[m], b[n], acc[m][n]);
        }
        __syncthreads();
    }

    int col0 = tx * 8;
    float4 bi0 = ((const float4*)bias)[tx * 2];
    float4 bi1 = ((const float4*)bias)[tx * 2 + 1];
    float bb[8] = {bi0.x, bi0.y, bi0.z, bi0.w, bi1.x, bi1.y, bi1.z, bi1.w};
    float ps[8], pq[8];
#pragma unroll
    for (int n = 0; n < 8; n++) { ps[n] = 0.f; pq[n] = 0.f; }

#pragma unroll
    for (int m = 0; m < 8; m++) {
        int gr = row0 + ty * 8 + m;
        if (gr < Nn) {
            float v[8];
#pragma unroll
            for (int n = 0; n < 8; n++) {
                v[n] = acc[m][n] + bb[n];
                ps[n] += v[n];
                pq[n] += v[n] * v[n];
            }
            *(float4*)(Out + (long)gr * Hh + col0)     = make_float4(v[0], v[1], v[2], v[3]);
            *(float4*)(Out + (long)gr * Hh + col0 + 4) = make_float4(v[4], v[5], v[6], v[7]);
        }
    }
#pragma unroll
    for (int n = 0; n < 8; n++) {
        atomicAdd(&shS[col0 + n], ps[n]);
        atomicAdd(&shQ[col0 + n], pq[n]);
    }
    __syncthreads();
    if (tid < Hh) {
        atomicAdd(&g_colS[tid], shS[tid]);
        atomicAdd(&g_colQ[tid], shQ[tid]);
    }
}

// ---------------- BN finalize -----------------------------------------------
__global__ void k_bnfin(const float* __restrict__ gamma,
                        const float* __restrict__ beta) {
    int j = threadIdx.x;
    if (j >= Hh) return;
    float inv = 1.0f / (float)Nn;
    float mu = g_colS[j] * inv;
    float var = g_colQ[j] * inv - mu * mu;
    float sc = gamma[j] * rsqrtf(var + BN_EPS);
    g_s[j] = sc;
    g_t[j] = beta[j] - sc * mu;
    g_colS[j] = 0.f;
    g_colQ[j] = 0.f;
}

// ---------------- post: h = relu(bn(A)); last layer pools -------------------
__global__ void k_post(int last, const int* __restrict__ batch) {
    int idx = blockIdx.x * blockDim.x + threadIdx.x;   // float4 id
    if (idx >= Nn * Hh / 4) return;
    int i = idx >> 5;
    int c = idx & 31;
    float4 z = ((const float4*)g_A)[idx];
    float4 s4 = ((const float4*)g_s)[c];
    float4 t4 = ((const float4*)g_t)[c];
    float4 v;
    v.x = fmaxf(fmaf(s4.x, z.x, t4.x), 0.f);
    v.y = fmaxf(fmaf(s4.y, z.y, t4.y), 0.f);
    v.z = fmaxf(fmaf(s4.z, z.z, t4.z), 0.f);
    v.w = fmaxf(fmaf(s4.w, z.w, t4.w), 0.f);
    if (!last) {
        ((float4*)g_h)[idx] = v;
    } else {
        int g = batch[i];
        float* p = g_pool + (long)g * Hh + c * 4;
        asm volatile("red.global.add.v4.f32 [%0], {%1,%2,%3,%4};"
                     :: "l"(p), "f"(v.x), "f"(v.y), "f"(v.z), "f"(v.w)
                     : "memory");
        if (c == 0) atomicAdd(&g_cnt[g], 1.0f);
    }
}

// ---------------- classifier ------------------------------------------------
__global__ void k_cls(const float* __restrict__ W,
                      const float* __restrict__ b,
                      float* __restrict__ out) {
    int tid = threadIdx.x;
    if (tid >= Gg * Cc) return;
    int g = tid >> 1;
    int cc = tid & 1;
    float inv = 1.0f / fmaxf(g_cnt[g], 1.0f);
    float acc = b[cc];
#pragma unroll 8
    for (int j = 0; j < Hh; j++)
        acc += g_pool[g * Hh + j] * inv * W[j * Cc + cc];
    out[g * Cc + cc] = acc;
}

// ---------------- launch ----------------------------------------------------
extern "C" void kernel_launch(void* const* d_in, const int* in_sizes, int n_in,
                              void* d_out, int out_size) {
    const float* x    = (const float*)d_in[0];
    const int*   ei   = (const int*)d_in[1];
    const int*   batch= (const int*)d_in[2];
    const float* encW = (const float*)d_in[3];
    const float* encb = (const float*)d_in[4];
    const float* W1   = (const float*)d_in[5];
    const float* b1   = (const float*)d_in[6];
    const float* g1   = (const float*)d_in[7];
    const float* be1  = (const float*)d_in[8];
    const float* W2   = (const float*)d_in[9];
    const float* b2   = (const float*)d_in[10];
    const float* eps  = (const float*)d_in[11];
    const float* bng  = (const float*)d_in[12];
    const float* bnb  = (const float*)d_in[13];
    const float* clsW = (const float*)d_in[14];
    const float* clsb = (const float*)d_in[15];
    float* out = (float*)d_out;

    float *pA = nullptr, *pB = nullptr;
    cudaGetSymbolAddress((void**)&pA, g_A);
    cudaGetSymbolAddress((void**)&pB, g_B);

    const int elemBlocks = (Nn * Hh / 4) / 256;          // 2500
    const int edgeBlocks = (Ee + 255) / 256;             // 2500
    const int gemmBlocks = (Nn + BM - 1) / BM;           // 157

    k_setup<<<80, 256>>>();
    k_hist<<<edgeBlocks, 256>>>(ei, x);
    k_scan<<<1, 1024>>>();
    k_fill<<<edgeBlocks, 256>>>(ei);
    k_prep<<<1, 128>>>(encW, encb, W1);

    // layer 1 (collapsed): z1 = a*u + c*v + b1 -> g_B
    k_l1<<<gemmBlocks, 128>>>(x, b1, eps);
    k_bnfin<<<1, 128>>>(g1, be1);
    k_gemm<<<gemmBlocks, 256>>>(pB, W2, b2, 1, pA);
    k_bnfin<<<1, 128>>>(bng, bnb);
    k_post<<<elemBlocks, 256>>>(0, batch);

    for (int l = 1; l < Ll; l++) {
        k_gather<<<Nn, 128>>>(eps, l);
        k_gemm<<<gemmBlocks, 256>>>(pA, W1 + (long)l * Hh * Hh, b1 + l * Hh, 0, pB);
        k_bnfin<<<1, 128>>>(g1 + l * Hh, be1 + l * Hh);
        k_gemm<<<gemmBlocks, 256>>>(pB, W2 + (long)l * Hh * Hh, b2 + l * Hh, 1, pA);
        k_bnfin<<<1, 128>>>(bng + l * Hh, bnb + l * Hh);
        k_post<<<elemBlocks, 256>>>((l == Ll - 1) ? 1 : 0, batch);
    }
    k_cls<<<1, 256>>>(clsW, clsb, out);
}

// round 3
// speedup vs baseline: 1.4116x; 1.0134x over previous
#include <cuda_runtime.h>
#include <cuda_bf16.h>

#define Nn 20000
#define Ee 640000
#define Hh 128
#define Gg 128
#define Cc 2
#define Ll 3
#define BN_EPS 1e-5f

// ---------------- scratch ---------------------------------------------------
__device__ float g_Z[Nn * Hh];      // raw gemm2 output (pre outer-BN)
__device__ float g_Y[Nn * Hh];      // gemm1 output (pre inner-BN)
__device__ float g_AGG[Nn * Hh];    // aggregated input to gemm1
__device__ float g_colS[Hh];
__device__ float g_colQ[Hh];
__device__ float g_s[Hh];
__device__ float g_t[Hh];
__device__ float g_pool[Gg * Hh];
__device__ float g_cnt[Gg];
__device__ int   g_deg[Nn];
__device__ float g_sx[Nn];
__device__ int   g_rowptr[Nn + 1];
__device__ int   g_cursor[Nn];
__device__ int   g_csrc[Ee];
__device__ float g_u[Hh];
__device__ float g_v[Hh];
__device__ unsigned g_ctr[8];

// ---------------- setup -----------------------------------------------------
__global__ void k_setup() {
    int idx = blockIdx.x * blockDim.x + threadIdx.x;
    for (int i = idx; i < Nn; i += gridDim.x * blockDim.x) {
        g_deg[i] = 0; g_sx[i] = 0.f;
    }
    for (int i = idx; i < Gg * Hh; i += gridDim.x * blockDim.x) g_pool[i] = 0.f;
    if (idx < Hh) { g_colS[idx] = 0.f; g_colQ[idx] = 0.f; }
    if (idx < Gg) g_cnt[idx] = 0.f;
    if (idx < 8) g_ctr[idx] = 0u;
}

// ---------------- histogram: deg[dst]++, sx[dst]+=x[src] --------------------
__global__ void k_hist(const int* __restrict__ ei, const float* __restrict__ x) {
    int e = blockIdx.x * blockDim.x + threadIdx.x;
    if (e >= Ee) return;
    int src = ei[e];
    int dst = ei[Ee + e];
    atomicAdd(&g_deg[dst], 1);
    atomicAdd(&g_sx[dst], x[src]);
}

// ---------------- scan (block 0) + prep u,v (block 1) -----------------------
#define SCAN_CH 20
__global__ void k_scan_prep(const float* __restrict__ encW,
                            const float* __restrict__ encb,
                            const float* __restrict__ W1) {
    if (blockIdx.x == 0) {
        __shared__ int sh[1024];
        int t = threadIdx.x;
        int base = t * SCAN_CH;
        int loc[SCAN_CH];
        int s = 0;
#pragma unroll
        for (int i = 0; i < SCAN_CH; i++) {
            int n = base + i;
            int d = (n < Nn) ? g_deg[n] : 0;
            loc[i] = s;
            s += d;
        }
        sh[t] = s;
        __syncthreads();
        for (int off = 1; off < 1024; off <<= 1) {
            int v = (t >= off) ? sh[t - off] : 0;
            __syncthreads();
            sh[t] += v;
            __syncthreads();
        }
        int excl = sh[t] - s;
#pragma unroll
        for (int i = 0; i < SCAN_CH; i++) {
            int n = base + i;
            if (n < Nn) {
                int r = excl + loc[i];
                g_rowptr[n] = r;
                g_cursor[n] = r;
            }
        }
        if (t == 1023) g_rowptr[Nn] = sh[1023];
    } else {
        int j = threadIdx.x;
        if (j < Hh) {
            float u = 0.f, v = 0.f;
#pragma unroll 8
            for (int k = 0; k < Hh; k++) {
                float w = W1[k * Hh + j];
                u = fmaf(encW[k], w, u);
                v = fmaf(encb[k], w, v);
            }
            g_u[j] = u;
            g_v[j] = v;
        }
    }
}

// ---------------- fill CSR --------------------------------------------------
__global__ void k_fill(const int* __restrict__ ei) {
    int e = blockIdx.x * blockDim.x + threadIdx.x;
    if (e >= Ee) return;
    int dst = ei[Ee + e];
    int p = atomicAdd(&g_cursor[dst], 1);
    g_csrc[p] = ei[e];
}

// ---------------- BN finalize (device helper, runs in last block) -----------
__device__ __forceinline__ void bn_finalize_tail(int tid, int gridN,
                                                 const float* gamma,
                                                 const float* beta,
                                                 int slot) {
    __threadfence();
    __syncthreads();
    __shared__ int isLast;
    if (tid == 0)
        isLast = (atomicAdd(&g_ctr[slot], 1u) == (unsigned)(gridN - 1)) ? 1 : 0;
    __syncthreads();
    if (isLast && tid < Hh) {
        __threadfence();
        float S = ((volatile float*)g_colS)[tid];
        float Q = ((volatile float*)g_colQ)[tid];
        float inv = 1.0f / (float)Nn;
        float mu = S * inv;
        float var = Q * inv - mu * mu;
        float sc = gamma[tid] * rsqrtf(var + BN_EPS);
        g_s[tid] = sc;
        g_t[tid] = beta[tid] - sc * mu;
        g_colS[tid] = 0.f;
        g_colQ[tid] = 0.f;
    }
}

// ---------------- layer-1 collapsed linear + BN stats + finalize ------------
// z1[i][j] = a_i*u[j] + c_i*v[j] + b1[j],  a=(1+e0)x+sx, c=(1+e0)+deg
__global__ void k_l1(const float* __restrict__ x,
                     const float* __restrict__ b1,
                     const float* __restrict__ eps,
                     const float* __restrict__ gamma,
                     const float* __restrict__ beta) {
    __shared__ float sa[128];
    __shared__ float sc_[128];
    int j = threadIdx.x;                  // 0..127 (column)
    int i0 = blockIdx.x * 128;
    float e0 = 1.0f + eps[0];
    {
        int i = i0 + j;
        if (i < Nn) {
            sa[j] = fmaf(e0, x[i], g_sx[i]);
            sc_[j] = e0 + (float)g_deg[i];
        }
    }
    __syncthreads();
    float u = g_u[j], v = g_v[j], bb = b1[j];
    float ps = 0.f, pq = 0.f;
    int rmax = min(128, Nn - i0);
#pragma unroll 4
    for (int r = 0; r < rmax; r++) {
        float z = fmaf(sa[r], u, fmaf(sc_[r], v, bb));
        g_Y[(long)(i0 + r) * Hh + j] = z;
        ps += z;
        pq += z * z;
    }
    atomicAdd(&g_colS[j], ps);
    atomicAdd(&g_colQ[j], pq);
    bn_finalize_tail(j, gridDim.x, gamma, beta, 0);
}

// ---------------- gather: AGG = (1+eps)*h_i + sum relu(bn(Z[src])) ----------
__global__ void k_gather(const float* __restrict__ Z,
                         float* __restrict__ AGG,
                         const float* __restrict__ eps, int l) {
    int warp = (blockIdx.x * blockDim.x + threadIdx.x) >> 5;
    int lane = threadIdx.x & 31;
    if (warp >= Nn) return;
    int i = warp;
    float4 s4 = ((const float4*)g_s)[lane];
    float4 t4 = ((const float4*)g_t)[lane];
    int start = g_rowptr[i];
    int end = g_rowptr[i + 1];
    float4 acc = make_float4(0.f, 0.f, 0.f, 0.f);
    int p = start;
    for (; p + 4 <= end; p += 4) {
        int s0 = g_csrc[p], s1 = g_csrc[p + 1], s2 = g_csrc[p + 2], s3 = g_csrc[p + 3];
        float4 z0 = *(const float4*)(Z + (long)s0 * Hh + lane * 4);
        float4 z1 = *(const float4*)(Z + (long)s1 * Hh + lane * 4);
        float4 z2 = *(const float4*)(Z + (long)s2 * Hh + lane * 4);
        float4 z3 = *(const float4*)(Z + (long)s3 * Hh + lane * 4);
        acc.x += fmaxf(fmaf(s4.x, z0.x, t4.x), 0.f) + fmaxf(fmaf(s4.x, z1.x, t4.x), 0.f)
               + fmaxf(fmaf(s4.x, z2.x, t4.x), 0.f) + fmaxf(fmaf(s4.x, z3.x, t4.x), 0.f);
        acc.y += fmaxf(fmaf(s4.y, z0.y, t4.y), 0.f) + fmaxf(fmaf(s4.y, z1.y, t4.y), 0.f)
               + fmaxf(fmaf(s4.y, z2.y, t4.y), 0.f) + fmaxf(fmaf(s4.y, z3.y, t4.y), 0.f);
        acc.z += fmaxf(fmaf(s4.z, z0.z, t4.z), 0.f) + fmaxf(fmaf(s4.z, z1.z, t4.z), 0.f)
               + fmaxf(fmaf(s4.z, z2.z, t4.z), 0.f) + fmaxf(fmaf(s4.z, z3.z, t4.z), 0.f);
        acc.w += fmaxf(fmaf(s4.w, z0.w, t4.w), 0.f) + fmaxf(fmaf(s4.w, z1.w, t4.w), 0.f)
               + fmaxf(fmaf(s4.w, z2.w, t4.w), 0.f) + fmaxf(fmaf(s4.w, z3.w, t4.w), 0.f);
    }
    for (; p < end; p++) {
        int s0 = g_csrc[p];
        float4 z0 = *(const float4*)(Z + (long)s0 * Hh + lane * 4);
        acc.x += fmaxf(fmaf(s4.x, z0.x, t4.x), 0.f);
        acc.y += fmaxf(fmaf(s4.y, z0.y, t4.y), 0.f);
        acc.z += fmaxf(fmaf(s4.z, z0.z, t4.z), 0.f);
        acc.w += fmaxf(fmaf(s4.w, z0.w, t4.w), 0.f);
    }
    // self term
    float4 zi = *(const float4*)(Z + (long)i * Hh + lane * 4);
    float el = 1.0f + eps[l];
    float4 o;
    o.x = fmaf(el, fmaxf(fmaf(s4.x, zi.x, t4.x), 0.f), acc.x);
    o.y = fmaf(el, fmaxf(fmaf(s4.y, zi.y, t4.y), 0.f), acc.y);
    o.z = fmaf(el, fmaxf(fmaf(s4.z, zi.z, t4.z), 0.f), acc.z);
    o.w = fmaf(el, fmaxf(fmaf(s4.w, zi.w, t4.w), 0.f), acc.w);
    *(float4*)(AGG + (long)i * Hh + lane * 4) = o;
}

// ---------------- GEMM: Out = preop(A) @ W + bias; BN stats + finalize ------
#define BM 128
#define BK 16
__global__ __launch_bounds__(256) void k_gemm(const float* __restrict__ A,
                                              const float* __restrict__ W,
                                              const float* __restrict__ bias,
                                              int usePre,
                                              float* __restrict__ Out,
                                              const float* __restrict__ gamma,
                                              const float* __restrict__ beta,
                                              int slot) {
    __shared__ float As[BK][132];
    __shared__ float Bs[BK][Hh];
    __shared__ float shS[Hh];
    __shared__ float shQ[Hh];

    int tid = threadIdx.x;
    int tx = tid & 15;
    int ty = tid >> 4;
    int row0 = blockIdx.x * BM;

    if (tid < Hh) { shS[tid] = 0.f; shQ[tid] = 0.f; }

    float acc[8][8];
#pragma unroll
    for (int m = 0; m < 8; m++)
#pragma unroll
        for (int n = 0; n < 8; n++) acc[m][n] = 0.f;

    for (int kk = 0; kk < Hh; kk += BK) {
#pragma unroll
        for (int q = 0; q < 2; q++) {
            int flat = tid * 2 + q;
            int r = flat >> 2;
            int k4 = flat & 3;
            int gr = row0 + r;
            float4 v = make_float4(0.f, 0.f, 0.f, 0.f);
            if (gr < Nn) {
                v = *(const float4*)(A + (long)gr * Hh + kk + k4 * 4);
                if (usePre) {
                    float4 s4 = *(const float4*)(g_s + kk + k4 * 4);
                    float4 t4 = *(const float4*)(g_t + kk + k4 * 4);
                    v.x = fmaxf(fmaf(s4.x, v.x, t4.x), 0.f);
                    v.y = fmaxf(fmaf(s4.y, v.y, t4.y), 0.f);
                    v.z = fmaxf(fmaf(s4.z, v.z, t4.z), 0.f);
                    v.w = fmaxf(fmaf(s4.w, v.w, t4.w), 0.f);
                }
            }
            As[k4 * 4 + 0][r] = v.x;
            As[k4 * 4 + 1][r] = v.y;
            As[k4 * 4 + 2][r] = v.z;
            As[k4 * 4 + 3][r] = v.w;
        }
#pragma unroll
        for (int q = 0; q < 2; q++) {
            int flat = tid * 2 + q;
            int kr = flat >> 5;
            int c4 = flat & 31;
            *(float4*)&Bs[kr][c4 * 4] = *(const float4*)(W + (long)(kk + kr) * Hh + c4 * 4);
        }
        __syncthreads();

#pragma unroll
        for (int k = 0; k < BK; k++) {
            float4 a0 = *(const float4*)&As[k][ty * 8];
            float4 a1 = *(const float4*)&As[k][ty * 8 + 4];
            float4 b0 = *(const float4*)&Bs[k][tx * 8];
            float4 b1 = *(const float4*)&Bs[k][tx * 8 + 4];
            float a[8] = {a0.x, a0.y, a0.z, a0.w, a1.x, a1.y, a1.z, a1.w};
            float b[8] = {b0.x, b0.y, b0.z, b0.w, b1.x, b1.y, b1.z, b1.w};
#pragma unroll
            for (int m = 0; m < 8; m++)
#pragma unroll
                for (int n = 0; n < 8; n++)
                    acc[m][n] = fmaf(a[m], b[n], acc[m][n]);
        }
        __syncthreads();
    }

    int col0 = tx * 8;
    float4 bi0 = ((const float4*)bias)[tx * 2];
    float4 bi1 = ((const float4*)bias)[tx * 2 + 1];
    float bb[8] = {bi0.x, bi0.y, bi0.z, bi0.w, bi1.x, bi1.y, bi1.z, bi1.w};
    float ps[8], pq[8];
#pragma unroll
    for (int n = 0; n < 8; n++) { ps[n] = 0.f; pq[n] = 0.f; }

#pragma unroll
    for (int m = 0; m < 8; m++) {
        int gr = row0 + ty * 8 + m;
        if (gr < Nn) {
            float v[8];
#pragma unroll
            for (int n = 0; n < 8; n++) {
                v[n] = acc[m][n] + bb[n];
                ps[n] += v[n];
                pq[n] += v[n] * v[n];
            }
            *(float4*)(Out + (long)gr * Hh + col0)     = make_float4(v[0], v[1], v[2], v[3]);
            *(float4*)(Out + (long)gr * Hh + col0 + 4) = make_float4(v[4], v[5], v[6], v[7]);
        }
    }
#pragma unroll
    for (int n = 0; n < 8; n++) {
        atomicAdd(&shS[col0 + n], ps[n]);
        atomicAdd(&shQ[col0 + n], pq[n]);
    }
    __syncthreads();
    if (tid < Hh) {
        atomicAdd(&g_colS[tid], shS[tid]);
        atomicAdd(&g_colQ[tid], shQ[tid]);
    }
    bn_finalize_tail(tid, gridDim.x, gamma, beta, slot);
}

// ---------------- final: pool( relu(bn(Z)) ) --------------------------------
__global__ void k_postpool(const float* __restrict__ Z,
                           const int* __restrict__ batch) {
    int idx = blockIdx.x * blockDim.x + threadIdx.x;   // float4 id
    if (idx >= Nn * Hh / 4) return;
    int i = idx >> 5;
    int c = idx & 31;
    float4 z = ((const float4*)Z)[idx];
    float4 s4 = ((const float4*)g_s)[c];
    float4 t4 = ((const float4*)g_t)[c];
    float4 v;
    v.x = fmaxf(fmaf(s4.x, z.x, t4.x), 0.f);
    v.y = fmaxf(fmaf(s4.y, z.y, t4.y), 0.f);
    v.z = fmaxf(fmaf(s4.z, z.z, t4.z), 0.f);
    v.w = fmaxf(fmaf(s4.w, z.w, t4.w), 0.f);
    int g = batch[i];
    float* p = g_pool + (long)g * Hh + c * 4;
    asm volatile("red.global.add.v4.f32 [%0], {%1,%2,%3,%4};"
                 :: "l"(p), "f"(v.x), "f"(v.y), "f"(v.z), "f"(v.w)
                 : "memory");
    if (c == 0) atomicAdd(&g_cnt[g], 1.0f);
}

// ---------------- classifier ------------------------------------------------
__global__ void k_cls(const float* __restrict__ W,
                      const float* __restrict__ b,
                      float* __restrict__ out) {
    int tid = threadIdx.x;
    if (tid >= Gg * Cc) return;
    int g = tid >> 1;
    int cc = tid & 1;
    float inv = 1.0f / fmaxf(g_cnt[g], 1.0f);
    float acc = b[cc];
#pragma unroll 8
    for (int j = 0; j < Hh; j++)
        acc += g_pool[g * Hh + j] * inv * W[j * Cc + cc];
    out[g * Cc + cc] = acc;
}

// ---------------- launch ----------------------------------------------------
extern "C" void kernel_launch(void* const* d_in, const int* in_sizes, int n_in,
                              void* d_out, int out_size) {
    const float* x    = (const float*)d_in[0];
    const int*   ei   = (const int*)d_in[1];
    const int*   batch= (const int*)d_in[2];
    const float* encW = (const float*)d_in[3];
    const float* encb = (const float*)d_in[4];
    const float* W1   = (const float*)d_in[5];
    const float* b1   = (const float*)d_in[6];
    const float* g1   = (const float*)d_in[7];
    const float* be1  = (const float*)d_in[8];
    const float* W2   = (const float*)d_in[9];
    const float* b2   = (const float*)d_in[10];
    const float* eps  = (const float*)d_in[11];
    const float* bng  = (const float*)d_in[12];
    const float* bnb  = (const float*)d_in[13];
    const float* clsW = (const float*)d_in[14];
    const float* clsb = (const float*)d_in[15];
    float* out = (float*)d_out;

    float *pZ = nullptr, *pY = nullptr, *pAGG = nullptr;
    cudaGetSymbolAddress((void**)&pZ, g_Z);
    cudaGetSymbolAddress((void**)&pY, g_Y);
    cudaGetSymbolAddress((void**)&pAGG, g_AGG);

    const int elemBlocks = (Nn * Hh / 4) / 256;          // 2500
    const int edgeBlocks = (Ee + 255) / 256;             // 2500
    const int gemmBlocks = (Nn + BM - 1) / BM;           // 157
    const int gathBlocks = (Nn + 7) / 8;                 // 2500 (8 warps/block)

    k_setup<<<80, 256>>>();
    k_hist<<<edgeBlocks, 256>>>(ei, x);
    k_scan_prep<<<2, 1024>>>(encW, encb, W1);
    k_fill<<<edgeBlocks, 256>>>(ei);

    // layer 0: collapsed gemm1, then gemm2
    k_l1<<<gemmBlocks, 128>>>(x, b1, eps, g1, be1);
    k_gemm<<<gemmBlocks, 256>>>(pY, W2, b2, 1, pZ, bng, bnb, 1);

    // layers 1..2
    for (int l = 1; l < Ll; l++) {
        k_gather<<<gathBlocks, 256>>>(pZ, pAGG, eps, l);
        k_gemm<<<gemmBlocks, 256>>>(pAGG, W1 + (long)l * Hh * Hh, b1 + l * Hh, 0,
                                    pY, g1 + l * Hh, be1 + l * Hh, 2 * l);
        k_gemm<<<gemmBlocks, 256>>>(pY, W2 + (long)l * Hh * Hh, b2 + l * Hh, 1,
                                    pZ, bng + l * Hh, bnb + l * Hh, 2 * l + 1);
    }

    k_postpool<<<elemBlocks, 256>>>(pZ, batch);
    k_cls<<<1, 256>>>(clsW, clsb, out);
}